// round 11
// baseline (speedup 1.0000x reference)
#include <cuda_runtime.h>
#include <cuda_fp16.h>
#include <cstdint>

#define NN 100000
#define MAXE 3200000
#define SCAN_B 100
#define SCAN_CH 1000

// ---- static scratch ----
__device__ int   g_is64;
__device__ int   g_deg[NN];
__device__ int   g_rowptr[NN + 1];
__device__ int   g_cursor[NN];
__device__ int   g_col[MAXE];
__device__ float g_dinv[NN];
__device__ int   g_bsum[SCAN_B];
__device__ int   g_scan_done;

// activations (fp16)
__device__ __half g_xw1h[(size_t)NN * 256];  // dinv-prescaled x@W1
__device__ __half g_xw2h[(size_t)NN * 128];  // dinv-prescaled z1@W2
__device__ __half g_z1h [(size_t)NN * 256];
__device__ __half g_z2h [(size_t)NN * 128];

// fp16 weights, [N,K] layout. heads = Wmu|Wlv stacked (256 x 128)
__device__ __half g_w1f[256 * 256];
__device__ __half g_w2f[128 * 256];
__device__ __half g_whf[256 * 128];

__device__ __forceinline__ const __half* sel_w(int id) {
    switch (id) { case 1: return g_w1f; case 2: return g_w2f; default: return g_whf; }
}
__device__ __forceinline__ const __half* sel_a16(int id) {
    return (id == 2) ? g_z1h : g_z2h;
}
__device__ __forceinline__ __half* sel_d16(int id) {
    return (id == 1) ? g_xw1h : g_xw2h;
}

__device__ __forceinline__ uint32_t smem_u32(const void* p) {
    uint32_t a;
    asm("{ .reg .u64 t; cvta.to.shared.u64 t, %1; cvt.u32.u64 %0, t; }"
        : "=r"(a) : "l"(p));
    return a;
}

#define LDSM4(r, addr)                                                         \
    asm volatile("ldmatrix.sync.aligned.m8n8.x4.shared.b16 {%0,%1,%2,%3}, [%4];" \
                 : "=r"((r)[0]), "=r"((r)[1]), "=r"((r)[2]), "=r"((r)[3])      \
                 : "r"(addr))

__device__ __forceinline__ void mma16816(float* c, const uint32_t* a,
                                         uint32_t b0, uint32_t b1) {
    asm volatile(
        "mma.sync.aligned.m16n8k16.row.col.f32.f16.f16.f32 "
        "{%0,%1,%2,%3}, {%4,%5,%6,%7}, {%8,%9}, {%0,%1,%2,%3};"
        : "+f"(c[0]), "+f"(c[1]), "+f"(c[2]), "+f"(c[3])
        : "r"(a[0]), "r"(a[1]), "r"(a[2]), "r"(a[3]), "r"(b0), "r"(b1));
}

// ================= prep =================
__global__ void k_init(const int* __restrict__ ei32, int E) {
    int i = blockIdx.x * blockDim.x + threadIdx.x;
    if (i < NN) g_deg[i] = 0;
    if (blockIdx.x == 0) {
        if (threadIdx.x == 0) g_scan_done = 0;
        __shared__ int bad;
        if (threadIdx.x == 0) bad = 0;
        __syncthreads();
        int n = min(E, 2048);
        for (int j = threadIdx.x; j < n; j += blockDim.x)
            if (ei32[2 * j + 1] != 0) bad = 1;
        __syncthreads();
        if (threadIdx.x == 0) g_is64 = bad ? 0 : 1;
    }
}
__device__ __forceinline__ int load_idx(const void* ei, long long pos) {
    if (g_is64) return (int)((const long long*)ei)[pos];
    return ((const int*)ei)[pos];
}

// k_count + weight convert fused: blocks [0, EB) count edges, [EB, EB+512) convert W
__global__ void k_count(const void* __restrict__ ei, int E, int EB,
                        const float* __restrict__ W1, const float* __restrict__ W2,
                        const float* __restrict__ Wmu, const float* __restrict__ Wlv) {
    int b = blockIdx.x;
    if (b < EB) {
        int e = b * 256 + threadIdx.x;
        if (e < E) {
            int r = load_idx(ei, e);
            if ((unsigned)r < NN) atomicAdd(&g_deg[r], 1);
        }
        return;
    }
    int w = b - EB;
    int t = threadIdx.x;
    float v;
    __half* dst;
    int i;
    if (w < 256) {                       // W1: 256x256 -> [N,K]
        i = w * 256 + t;
        int n = i >> 8, k = i & 255;
        v = W1[(size_t)k * 256 + n];
        dst = g_w1f;
    } else if (w < 384) {                // W2: [N=128,K=256]
        i = (w - 256) * 256 + t;
        int n = i >> 8, k = i & 255;
        v = W2[(size_t)k * 128 + n];
        dst = g_w2f;
    } else {                             // heads: [N=256,K=128]
        i = (w - 384) * 256 + t;
        int n = i >> 7, k = i & 127;
        v = (n < 128) ? Wmu[(size_t)k * 128 + n] : Wlv[(size_t)k * 128 + (n - 128)];
        dst = g_whf;
    }
    dst[i] = __float2half_rn(v);
}

// merged reduce + scan: publish block sums, spin until all published, then scan.
__global__ void k_scan() {
    __shared__ int sh[256];
    __shared__ int ps[256];
    __shared__ int blkoff;
    int b = blockIdx.x, t = threadIdx.x, base = b * SCAN_CH;

    // phase A: block sum of g_deg[base .. base+999]
    int s = 0;
    for (int i = t; i < SCAN_CH; i += 256) s += g_deg[base + i];
    sh[t] = s;
    __syncthreads();
    for (int off = 128; off > 0; off >>= 1) {
        if (t < off) sh[t] += sh[t + off];
        __syncthreads();
    }
    if (t == 0) {
        g_bsum[b] = sh[0];
        __threadfence();
        atomicAdd(&g_scan_done, 1);
        // spin until all 100 block sums are visible (all blocks resident)
        while (atomicAdd(&g_scan_done, 0) < SCAN_B) {}
        int o = 0;
        for (int j = 0; j < b; j++) o += g_bsum[j];
        blkoff = o;
        if (b == SCAN_B - 1) g_rowptr[NN] = o + g_bsum[b];
    }
    __syncthreads();

    // phase B: local exclusive scan + outputs
    int d[4], my = 0;
    if (t < 250) {
#pragma unroll
        for (int j = 0; j < 4; j++) { d[j] = g_deg[base + t * 4 + j]; my += d[j]; }
    }
    ps[t] = my;
    __syncthreads();
    for (int off = 1; off < 256; off <<= 1) {
        int u = (t >= off) ? ps[t - off] : 0;
        __syncthreads();
        ps[t] += u;
        __syncthreads();
    }
    if (t < 250) {
        int run = blkoff + ps[t] - my;
#pragma unroll
        for (int j = 0; j < 4; j++) {
            int i = base + t * 4 + j;
            g_rowptr[i] = run;
            g_cursor[i] = run;
            g_dinv[i]   = rsqrtf((float)(d[j] + 1));
            run += d[j];
        }
    }
}
__global__ void k_fill(const void* __restrict__ ei, int E) {
    int e = blockIdx.x * blockDim.x + threadIdx.x;
    if (e < E) {
        int r = load_idx(ei, e);
        if ((unsigned)r < NN) {
            int c = load_idx(ei, (long long)E + e);
            if ((unsigned)c >= NN) c = 0;
            int p = atomicAdd(&g_cursor[r], 1);
            g_col[p] = c;
        }
    }
}

// ================= fp16 mma.sync GEMM (distance-2 prefetch) =================
#define ROWB 48
#define MATB (128 * ROWB)      // 6144
#define STAGEB (2 * MATB)      // 12288

template <int ASRC, bool A16, int WID, int OUT16, bool BIAS, bool HEADS, int NT, int KK>
__global__ void __launch_bounds__(256, 2)
k_mgemm(const float* __restrict__ Aarg, const float* __restrict__ bias,
        const float* __restrict__ bias2, float* __restrict__ Carg) {
    __shared__ __align__(16) unsigned char smem[2 * STAGEB];

    const float*  Af = A16 ? nullptr : Aarg;
    const __half* Ah = A16 ? sel_a16(ASRC) : nullptr;
    const __half* W  = sel_w(WID);

    int tid = threadIdx.x;
    int wid = tid >> 5, lane = tid & 31;
    int wm = wid & 3, wn = wid >> 2;
    int bm = blockIdx.y * 128, bn = blockIdx.x * 128;

    int grow = tid >> 1;
    int gkq  = (tid & 1) * 8;
    bool aval = (bm + grow) < NN;
    const float*  Apf = A16 ? nullptr : (Af + (size_t)(bm + grow) * KK + gkq);
    const __half* Aph = A16 ? (Ah + (size_t)(bm + grow) * KK + gkq) : nullptr;
    const __half* Bp  = W + (size_t)(bn + grow) * KK + gkq;

    uint32_t sb = smem_u32(smem);
    uint32_t stA = sb + grow * ROWB + gkq * 2;
    uint32_t stB = sb + MATB + grow * ROWB + gkq * 2;

    int lrow = lane & 15, lcolb = (lane >> 4) * 16;
    uint32_t ldA = sb + (wm * 32 + lrow) * ROWB + lcolb;
    uint32_t ldB = sb + MATB + (wn * 64 + lrow) * ROWB + lcolb;

    float c[2][8][4];
#pragma unroll
    for (int i = 0; i < 2; i++)
#pragma unroll
        for (int j = 0; j < 8; j++)
#pragma unroll
            for (int q = 0; q < 4; q++) c[i][j][q] = 0.f;

    uint4 abuf, bbuf;
    auto gload = [&](int k0) {
        if (A16) {
            abuf = aval ? *(const uint4*)(Aph + k0) : make_uint4(0u, 0u, 0u, 0u);
        } else {
            float4 v0 = aval ? *(const float4*)(Apf + k0)     : make_float4(0.f, 0.f, 0.f, 0.f);
            float4 v1 = aval ? *(const float4*)(Apf + k0 + 4) : make_float4(0.f, 0.f, 0.f, 0.f);
            __half2 h0 = __floats2half2_rn(v0.x, v0.y);
            __half2 h1 = __floats2half2_rn(v0.z, v0.w);
            __half2 h2 = __floats2half2_rn(v1.x, v1.y);
            __half2 h3 = __floats2half2_rn(v1.z, v1.w);
            abuf.x = *(uint32_t*)&h0; abuf.y = *(uint32_t*)&h1;
            abuf.z = *(uint32_t*)&h2; abuf.w = *(uint32_t*)&h3;
        }
        bbuf = *(const uint4*)(Bp + k0);
    };
    auto sstore = [&](int s) {
        uint32_t base = s * STAGEB;
        *(uint4*)(smem + (stA - sb) + base) = abuf;
        *(uint4*)(smem + (stB - sb) + base) = bbuf;
    };

    const int NSTEP = KK / 16;
    // prologue: stage0 = k0; regs hold k1 (distance-2)
    gload(0);
    sstore(0);
    if (NSTEP > 1) gload(16);
    __syncthreads();

    int s = 0;
    for (int step = 0; step < NSTEP; step++) {
        uint32_t base = s * STAGEB;
        uint32_t af[2][4];
#pragma unroll
        for (int mt = 0; mt < 2; mt++)
            LDSM4(af[mt], ldA + base + mt * 16 * ROWB);
        uint32_t bf[4][4];
#pragma unroll
        for (int g = 0; g < 4; g++)
            LDSM4(bf[g], ldB + base + g * 16 * ROWB);
#pragma unroll
        for (int mt = 0; mt < 2; mt++)
#pragma unroll
            for (int g = 0; g < 4; g++) {
                mma16816(c[mt][g * 2],     af[mt], bf[g][0], bf[g][2]);
                mma16816(c[mt][g * 2 + 1], af[mt], bf[g][1], bf[g][3]);
            }
        if (step + 1 < NSTEP) {
            sstore(s ^ 1);                       // k_{step+1} from regs
            if (step + 2 < NSTEP) gload((step + 2) * 16);  // prefetch k_{step+2}
        }
        __syncthreads();
        s ^= 1;
    }

    // ---- epilogue: OUT16 paths prescale by dinv[r] ----
    const float* bs = (HEADS && bn >= 128) ? bias2 : bias;
    float* cbase = HEADS ? (Carg + (bn >= 128 ? (size_t)NN * 128 : 0)) : Carg;
#pragma unroll
    for (int mt = 0; mt < 2; mt++) {
#pragma unroll
        for (int n8 = 0; n8 < 8; n8++) {
            int col = bn + wn * 64 + n8 * 8 + (lane & 3) * 2;
            int lcol = HEADS ? (col & 127) : col;
#pragma unroll
            for (int h = 0; h < 2; h++) {
                int r = bm + wm * 32 + mt * 16 + (lane >> 2) + h * 8;
                if (r >= NN) continue;
                float v0 = c[mt][n8][2 * h], v1 = c[mt][n8][2 * h + 1];
                if (OUT16 != 0) {
                    float sc = g_dinv[r];
                    __half2 hv = __floats2half2_rn(v0 * sc, v1 * sc);
                    *(__half2*)(sel_d16(OUT16) + (size_t)r * NT + col) = hv;
                } else {
                    if (BIAS) { v0 += bs[lcol]; v1 += bs[lcol + 1]; }
                    int nt = HEADS ? 128 : NT;
                    *(float2*)(cbase + (size_t)r * nt + lcol) = make_float2(v0, v1);
                }
            }
        }
    }
}

// ================= propagate: fp16 gather (prescaled), fp16 out =================
template <int F, bool RELU, int SRC, int DST>
__global__ void k_prop(const float* __restrict__ bias) {
    const int L = F / 8;
    int node = blockIdx.x * blockDim.y + threadIdx.y;
    if (node >= NN) return;
    const uint4* xw = (const uint4*)((SRC == 1) ? g_xw1h : g_xw2h);
    __half* z = (DST == 1) ? g_z1h : g_z2h;
    int f = threadIdx.x;

    float2 a0 = {0.f, 0.f}, a1 = {0.f, 0.f}, a2 = {0.f, 0.f}, a3 = {0.f, 0.f};
    auto accum = [&](uint4 u) {
        float2 t;
        t = __half22float2(*(__half2*)&u.x); a0.x += t.x; a0.y += t.y;
        t = __half22float2(*(__half2*)&u.y); a1.x += t.x; a1.y += t.y;
        t = __half22float2(*(__half2*)&u.z); a2.x += t.x; a2.y += t.y;
        t = __half22float2(*(__half2*)&u.w); a3.x += t.x; a3.y += t.y;
    };
    accum(xw[(size_t)node * L + f]);  // self loop (prescaled)

    int s = g_rowptr[node], e = g_rowptr[node + 1];
    int k = s;
    for (; k + 4 <= e; k += 4) {
        int c0 = __ldg(&g_col[k + 0]);
        int c1 = __ldg(&g_col[k + 1]);
        int c2 = __ldg(&g_col[k + 2]);
        int c3 = __ldg(&g_col[k + 3]);
        uint4 u0 = xw[(size_t)c0 * L + f];
        uint4 u1 = xw[(size_t)c1 * L + f];
        uint4 u2 = xw[(size_t)c2 * L + f];
        uint4 u3 = xw[(size_t)c3 * L + f];
        accum(u0); accum(u1); accum(u2); accum(u3);
    }
    for (; k < e; k++) {
        int c = __ldg(&g_col[k]);
        accum(xw[(size_t)c * L + f]);
    }

    float di = g_dinv[node];
    float4 b0 = *(const float4*)(bias + f * 8);
    float4 b1 = *(const float4*)(bias + f * 8 + 4);
    float o[8];
    o[0] = di * a0.x + b0.x; o[1] = di * a0.y + b0.y;
    o[2] = di * a1.x + b0.z; o[3] = di * a1.y + b0.w;
    o[4] = di * a2.x + b1.x; o[5] = di * a2.y + b1.y;
    o[6] = di * a3.x + b1.z; o[7] = di * a3.y + b1.w;
    if (RELU) {
#pragma unroll
        for (int j = 0; j < 8; j++) o[j] = fmaxf(o[j], 0.f);
    }
    __half2 p0 = __floats2half2_rn(o[0], o[1]);
    __half2 p1 = __floats2half2_rn(o[2], o[3]);
    __half2 p2 = __floats2half2_rn(o[4], o[5]);
    __half2 p3 = __floats2half2_rn(o[6], o[7]);
    uint4 pk;
    pk.x = *(uint32_t*)&p0; pk.y = *(uint32_t*)&p1;
    pk.z = *(uint32_t*)&p2; pk.w = *(uint32_t*)&p3;
    *(uint4*)(z + (size_t)node * F + f * 8) = pk;
}

// ================= launch (single stream) =================
extern "C" void kernel_launch(void* const* d_in, const int* in_sizes, int n_in,
                              void* d_out, int out_size) {
    const float* x   = (const float*)d_in[0];
    const void*  ei  = d_in[1];
    const float* W1  = (const float*)d_in[2];
    const float* b1  = (const float*)d_in[3];
    const float* W2  = (const float*)d_in[4];
    const float* b2  = (const float*)d_in[5];
    const float* Wmu = (const float*)d_in[6];
    const float* bmu = (const float*)d_in[7];
    const float* Wlv = (const float*)d_in[8];
    const float* blv = (const float*)d_in[9];
    float* out = (float*)d_out;

    int E = in_sizes[1] / 2;
    int EB = (E + 255) / 256;
    const int GM = (NN + 127) / 128;  // 782

    // graph prep + weight convert (4 launches)
    k_init<<<(NN + 255) / 256, 256>>>((const int*)ei, E);
    k_count<<<EB + 512, 256>>>(ei, E, EB, W1, W2, Wmu, Wlv);
    k_scan<<<SCAN_B, 256>>>();
    k_fill<<<EB, 256>>>(ei, E);

    // layer 1
    k_mgemm<0, false, 1, 1, false, false, 256, 256><<<dim3(2, GM), 256>>>(x, nullptr, nullptr, nullptr);
    k_prop<256, true, 1, 1><<<(NN + 7) / 8, dim3(32, 8)>>>(b1);

    // layer 2
    k_mgemm<2, true, 2, 2, false, false, 128, 256><<<dim3(1, GM), 256>>>(nullptr, nullptr, nullptr, nullptr);
    k_prop<128, false, 2, 2><<<(NN + 15) / 16, dim3(16, 16)>>>(b2);

    // merged heads
    k_mgemm<4, true, 3, 0, true, true, 128, 128><<<dim3(2, GM), 256>>>(nullptr, bmu, blv, out);
}

// round 12
// speedup vs baseline: 1.4674x; 1.4674x over previous
#include <cuda_runtime.h>
#include <cuda_fp16.h>
#include <cstdint>

#define NN 100000
#define MAXE 3200000
#define SCAN_B 100
#define SCAN_CH 1000

// ---- static scratch ----
__device__ int   g_is64;
__device__ int   g_deg[NN];
__device__ int   g_rowptr[NN + 1];
__device__ int   g_cursor[NN];
__device__ int   g_col[MAXE];
__device__ float g_dinv[NN];
__device__ int   g_bsum[SCAN_B];

// activations (fp16)
__device__ __half g_xw1h[(size_t)NN * 256];  // dinv-prescaled x@W1
__device__ __half g_xw2h[(size_t)NN * 128];  // dinv-prescaled z1@W2
__device__ __half g_z1h [(size_t)NN * 256];
__device__ __half g_z2h [(size_t)NN * 128];

// fp16 weights, [N,K] layout. heads = Wmu|Wlv stacked (256 x 128)
__device__ __half g_w1f[256 * 256];
__device__ __half g_w2f[128 * 256];
__device__ __half g_whf[256 * 128];

__device__ __forceinline__ const __half* sel_w(int id) {
    switch (id) { case 1: return g_w1f; case 2: return g_w2f; default: return g_whf; }
}
__device__ __forceinline__ const __half* sel_a16(int id) {
    return (id == 2) ? g_z1h : g_z2h;
}
__device__ __forceinline__ __half* sel_d16(int id) {
    return (id == 1) ? g_xw1h : g_xw2h;
}

__device__ __forceinline__ uint32_t smem_u32(const void* p) {
    uint32_t a;
    asm("{ .reg .u64 t; cvta.to.shared.u64 t, %1; cvt.u32.u64 %0, t; }"
        : "=r"(a) : "l"(p));
    return a;
}

#define LDSM4(r, addr)                                                         \
    asm volatile("ldmatrix.sync.aligned.m8n8.x4.shared.b16 {%0,%1,%2,%3}, [%4];" \
                 : "=r"((r)[0]), "=r"((r)[1]), "=r"((r)[2]), "=r"((r)[3])      \
                 : "r"(addr))

__device__ __forceinline__ void mma16816(float* c, const uint32_t* a,
                                         uint32_t b0, uint32_t b1) {
    asm volatile(
        "mma.sync.aligned.m16n8k16.row.col.f32.f16.f16.f32 "
        "{%0,%1,%2,%3}, {%4,%5,%6,%7}, {%8,%9}, {%0,%1,%2,%3};"
        : "+f"(c[0]), "+f"(c[1]), "+f"(c[2]), "+f"(c[3])
        : "r"(a[0]), "r"(a[1]), "r"(a[2]), "r"(a[3]), "r"(b0), "r"(b1));
}

// ================= prep =================
__global__ void k_init(const int* __restrict__ ei32, int E) {
    int i = blockIdx.x * blockDim.x + threadIdx.x;
    if (i < NN) g_deg[i] = 0;
    if (blockIdx.x == 0) {
        __shared__ int bad;
        if (threadIdx.x == 0) bad = 0;
        __syncthreads();
        int n = min(E, 2048);
        for (int j = threadIdx.x; j < n; j += blockDim.x)
            if (ei32[2 * j + 1] != 0) bad = 1;
        __syncthreads();
        if (threadIdx.x == 0) g_is64 = bad ? 0 : 1;
    }
}
__device__ __forceinline__ int load_idx(const void* ei, long long pos) {
    if (g_is64) return (int)((const long long*)ei)[pos];
    return ((const int*)ei)[pos];
}

// k_count + weight convert fused: blocks [0, EB) count edges, [EB, EB+512) convert W
__global__ void k_count(const void* __restrict__ ei, int E, int EB,
                        const float* __restrict__ W1, const float* __restrict__ W2,
                        const float* __restrict__ Wmu, const float* __restrict__ Wlv) {
    int b = blockIdx.x;
    if (b < EB) {
        int e = b * 256 + threadIdx.x;
        if (e < E) {
            int r = load_idx(ei, e);
            if ((unsigned)r < NN) atomicAdd(&g_deg[r], 1);
        }
        return;
    }
    int w = b - EB;
    int t = threadIdx.x;
    float v;
    __half* dst;
    int i;
    if (w < 256) {                       // W1 -> [N=256,K=256]
        i = w * 256 + t;
        int n = i >> 8, k = i & 255;
        v = W1[(size_t)k * 256 + n];
        dst = g_w1f;
    } else if (w < 384) {                // W2 -> [N=128,K=256]
        i = (w - 256) * 256 + t;
        int n = i >> 8, k = i & 255;
        v = W2[(size_t)k * 128 + n];
        dst = g_w2f;
    } else {                             // heads -> [N=256,K=128]
        i = (w - 384) * 256 + t;
        int n = i >> 7, k = i & 127;
        v = (n < 128) ? Wmu[(size_t)k * 128 + n] : Wlv[(size_t)k * 128 + (n - 128)];
        dst = g_whf;
    }
    dst[i] = __float2half_rn(v);
}
__global__ void k_reduce() {
    __shared__ int sh[256];
    int b = blockIdx.x, t = threadIdx.x, s = 0, base = b * SCAN_CH;
    for (int i = t; i < SCAN_CH; i += 256) s += g_deg[base + i];
    sh[t] = s;
    __syncthreads();
    for (int off = 128; off > 0; off >>= 1) {
        if (t < off) sh[t] += sh[t + off];
        __syncthreads();
    }
    if (t == 0) g_bsum[b] = sh[0];
}
__global__ void k_scan_final() {
    __shared__ int ps[256];
    __shared__ int blkoff;
    int b = blockIdx.x, t = threadIdx.x, base = b * SCAN_CH;
    if (t == 0) {
        int o = 0;
        for (int j = 0; j < b; j++) o += g_bsum[j];
        blkoff = o;
        if (b == SCAN_B - 1) g_rowptr[NN] = o + g_bsum[b];
    }
    int d[4], my = 0;
    if (t < 250) {
#pragma unroll
        for (int j = 0; j < 4; j++) { d[j] = g_deg[base + t * 4 + j]; my += d[j]; }
    }
    ps[t] = my;
    __syncthreads();
    for (int off = 1; off < 256; off <<= 1) {
        int u = (t >= off) ? ps[t - off] : 0;
        __syncthreads();
        ps[t] += u;
        __syncthreads();
    }
    if (t < 250) {
        int run = blkoff + ps[t] - my;
#pragma unroll
        for (int j = 0; j < 4; j++) {
            int i = base + t * 4 + j;
            g_rowptr[i] = run;
            g_cursor[i] = run;
            g_dinv[i]   = rsqrtf((float)(d[j] + 1));
            run += d[j];
        }
    }
}
__global__ void k_fill(const void* __restrict__ ei, int E) {
    int e = blockIdx.x * blockDim.x + threadIdx.x;
    if (e < E) {
        int r = load_idx(ei, e);
        if ((unsigned)r < NN) {
            int c = load_idx(ei, (long long)E + e);
            if ((unsigned)c >= NN) c = 0;
            int p = atomicAdd(&g_cursor[r], 1);
            g_col[p] = c;
        }
    }
}

// ================= fp16 mma.sync GEMM (R10 pipeline) =================
#define ROWB 48
#define MATB (128 * ROWB)      // 6144
#define STAGEB (2 * MATB)      // 12288

template <int ASRC, bool A16, int WID, int OUT16, bool BIAS, bool HEADS, int NT, int KK>
__global__ void __launch_bounds__(256, 2)
k_mgemm(const float* __restrict__ Aarg, const float* __restrict__ bias,
        const float* __restrict__ bias2, float* __restrict__ Carg) {
    __shared__ __align__(16) unsigned char smem[2 * STAGEB];

    const float*  Af = A16 ? nullptr : Aarg;
    const __half* Ah = A16 ? sel_a16(ASRC) : nullptr;
    const __half* W  = sel_w(WID);

    int tid = threadIdx.x;
    int wid = tid >> 5, lane = tid & 31;
    int wm = wid & 3, wn = wid >> 2;
    int bm = blockIdx.y * 128, bn = blockIdx.x * 128;

    int grow = tid >> 1;
    int gkq  = (tid & 1) * 8;
    bool aval = (bm + grow) < NN;
    const float*  Apf = A16 ? nullptr : (Af + (size_t)(bm + grow) * KK + gkq);
    const __half* Aph = A16 ? (Ah + (size_t)(bm + grow) * KK + gkq) : nullptr;
    const __half* Bp  = W + (size_t)(bn + grow) * KK + gkq;

    uint32_t sb = smem_u32(smem);
    uint32_t stA = sb + grow * ROWB + gkq * 2;
    uint32_t stB = sb + MATB + grow * ROWB + gkq * 2;

    int lrow = lane & 15, lcolb = (lane >> 4) * 16;
    uint32_t ldA = sb + (wm * 32 + lrow) * ROWB + lcolb;
    uint32_t ldB = sb + MATB + (wn * 64 + lrow) * ROWB + lcolb;

    float c[2][8][4];
#pragma unroll
    for (int i = 0; i < 2; i++)
#pragma unroll
        for (int j = 0; j < 8; j++)
#pragma unroll
            for (int q = 0; q < 4; q++) c[i][j][q] = 0.f;

    uint4 abuf, bbuf;
    auto gload = [&](int k0) {
        if (A16) {
            abuf = aval ? *(const uint4*)(Aph + k0) : make_uint4(0u, 0u, 0u, 0u);
        } else {
            float4 v0 = aval ? *(const float4*)(Apf + k0)     : make_float4(0.f, 0.f, 0.f, 0.f);
            float4 v1 = aval ? *(const float4*)(Apf + k0 + 4) : make_float4(0.f, 0.f, 0.f, 0.f);
            __half2 h0 = __floats2half2_rn(v0.x, v0.y);
            __half2 h1 = __floats2half2_rn(v0.z, v0.w);
            __half2 h2 = __floats2half2_rn(v1.x, v1.y);
            __half2 h3 = __floats2half2_rn(v1.z, v1.w);
            abuf.x = *(uint32_t*)&h0; abuf.y = *(uint32_t*)&h1;
            abuf.z = *(uint32_t*)&h2; abuf.w = *(uint32_t*)&h3;
        }
        bbuf = *(const uint4*)(Bp + k0);
    };
    auto sstore = [&](int s) {
        uint32_t base = s * STAGEB;
        *(uint4*)(smem + (stA - sb) + base) = abuf;
        *(uint4*)(smem + (stB - sb) + base) = bbuf;
    };

    gload(0);
    sstore(0);

    const int NSTEP = KK / 16;
    int s = 0;
    for (int step = 0; step < NSTEP; step++) {
        __syncthreads();
        bool more = (step + 1) < NSTEP;
        if (more) gload((step + 1) * 16);

        uint32_t base = s * STAGEB;
        uint32_t af[2][4];
#pragma unroll
        for (int mt = 0; mt < 2; mt++)
            LDSM4(af[mt], ldA + base + mt * 16 * ROWB);
        uint32_t bf[4][4];
#pragma unroll
        for (int g = 0; g < 4; g++)
            LDSM4(bf[g], ldB + base + g * 16 * ROWB);
#pragma unroll
        for (int mt = 0; mt < 2; mt++)
#pragma unroll
            for (int g = 0; g < 4; g++) {
                mma16816(c[mt][g * 2],     af[mt], bf[g][0], bf[g][2]);
                mma16816(c[mt][g * 2 + 1], af[mt], bf[g][1], bf[g][3]);
            }
        if (more) sstore(s ^ 1);
        s ^= 1;
    }

    // ---- epilogue: OUT16 paths prescale by dinv[r] ----
    const float* bs = (HEADS && bn >= 128) ? bias2 : bias;
    float* cbase = HEADS ? (Carg + (bn >= 128 ? (size_t)NN * 128 : 0)) : Carg;
#pragma unroll
    for (int mt = 0; mt < 2; mt++) {
#pragma unroll
        for (int n8 = 0; n8 < 8; n8++) {
            int col = bn + wn * 64 + n8 * 8 + (lane & 3) * 2;
            int lcol = HEADS ? (col & 127) : col;
#pragma unroll
            for (int h = 0; h < 2; h++) {
                int r = bm + wm * 32 + mt * 16 + (lane >> 2) + h * 8;
                if (r >= NN) continue;
                float v0 = c[mt][n8][2 * h], v1 = c[mt][n8][2 * h + 1];
                if (OUT16 != 0) {
                    float sc = g_dinv[r];
                    __half2 hv = __floats2half2_rn(v0 * sc, v1 * sc);
                    *(__half2*)(sel_d16(OUT16) + (size_t)r * NT + col) = hv;
                } else {
                    if (BIAS) { v0 += bs[lcol]; v1 += bs[lcol + 1]; }
                    int nt = HEADS ? 128 : NT;
                    *(float2*)(cbase + (size_t)r * nt + lcol) = make_float2(v0, v1);
                }
            }
        }
    }
}

// ================= propagate: fp16 gather (prescaled), fp16 out =================
template <int F, bool RELU, int SRC, int DST>
__global__ void k_prop(const float* __restrict__ bias) {
    const int L = F / 8;
    int node = blockIdx.x * blockDim.y + threadIdx.y;
    if (node >= NN) return;
    const uint4* xw = (const uint4*)((SRC == 1) ? g_xw1h : g_xw2h);
    __half* z = (DST == 1) ? g_z1h : g_z2h;
    int f = threadIdx.x;

    float2 a0 = {0.f, 0.f}, a1 = {0.f, 0.f}, a2 = {0.f, 0.f}, a3 = {0.f, 0.f};
    auto accum = [&](uint4 u) {
        float2 t;
        t = __half22float2(*(__half2*)&u.x); a0.x += t.x; a0.y += t.y;
        t = __half22float2(*(__half2*)&u.y); a1.x += t.x; a1.y += t.y;
        t = __half22float2(*(__half2*)&u.z); a2.x += t.x; a2.y += t.y;
        t = __half22float2(*(__half2*)&u.w); a3.x += t.x; a3.y += t.y;
    };
    accum(xw[(size_t)node * L + f]);  // self loop (prescaled)

    int s = g_rowptr[node], e = g_rowptr[node + 1];
    int k = s;
    for (; k + 4 <= e; k += 4) {
        int c0 = __ldg(&g_col[k + 0]);
        int c1 = __ldg(&g_col[k + 1]);
        int c2 = __ldg(&g_col[k + 2]);
        int c3 = __ldg(&g_col[k + 3]);
        uint4 u0 = xw[(size_t)c0 * L + f];
        uint4 u1 = xw[(size_t)c1 * L + f];
        uint4 u2 = xw[(size_t)c2 * L + f];
        uint4 u3 = xw[(size_t)c3 * L + f];
        accum(u0); accum(u1); accum(u2); accum(u3);
    }
    for (; k < e; k++) {
        int c = __ldg(&g_col[k]);
        accum(xw[(size_t)c * L + f]);
    }

    float di = g_dinv[node];
    float4 b0 = *(const float4*)(bias + f * 8);
    float4 b1 = *(const float4*)(bias + f * 8 + 4);
    float o[8];
    o[0] = di * a0.x + b0.x; o[1] = di * a0.y + b0.y;
    o[2] = di * a1.x + b0.z; o[3] = di * a1.y + b0.w;
    o[4] = di * a2.x + b1.x; o[5] = di * a2.y + b1.y;
    o[6] = di * a3.x + b1.z; o[7] = di * a3.y + b1.w;
    if (RELU) {
#pragma unroll
        for (int j = 0; j < 8; j++) o[j] = fmaxf(o[j], 0.f);
    }
    __half2 p0 = __floats2half2_rn(o[0], o[1]);
    __half2 p1 = __floats2half2_rn(o[2], o[3]);
    __half2 p2 = __floats2half2_rn(o[4], o[5]);
    __half2 p3 = __floats2half2_rn(o[6], o[7]);
    uint4 pk;
    pk.x = *(uint32_t*)&p0; pk.y = *(uint32_t*)&p1;
    pk.z = *(uint32_t*)&p2; pk.w = *(uint32_t*)&p3;
    *(uint4*)(z + (size_t)node * F + f * 8) = pk;
}

// ================= stream/event resources =================
struct Aux {
    cudaStream_t s2 = nullptr;
    cudaEvent_t  evScan = nullptr, evJoin = nullptr;
    bool ok = false;
    Aux() {
        ok = (cudaStreamCreateWithFlags(&s2, cudaStreamNonBlocking) == cudaSuccess) &&
             (cudaEventCreateWithFlags(&evScan, cudaEventDisableTiming) == cudaSuccess) &&
             (cudaEventCreateWithFlags(&evJoin, cudaEventDisableTiming) == cudaSuccess);
    }
};
static Aux g_aux;

// ================= launch =================
extern "C" void kernel_launch(void* const* d_in, const int* in_sizes, int n_in,
                              void* d_out, int out_size) {
    const float* x   = (const float*)d_in[0];
    const void*  ei  = d_in[1];
    const float* W1  = (const float*)d_in[2];
    const float* b1  = (const float*)d_in[3];
    const float* W2  = (const float*)d_in[4];
    const float* b2  = (const float*)d_in[5];
    const float* Wmu = (const float*)d_in[6];
    const float* bmu = (const float*)d_in[7];
    const float* Wlv = (const float*)d_in[8];
    const float* blv = (const float*)d_in[9];
    float* out = (float*)d_out;

    int E = in_sizes[1] / 2;
    int EB = (E + 255) / 256;
    const int GM = (NN + 127) / 128;  // 782

    // graph prep + fused weight convert
    k_init<<<(NN + 255) / 256, 256>>>((const int*)ei, E);
    k_count<<<EB + 512, 256>>>(ei, E, EB, W1, W2, Wmu, Wlv);
    k_reduce<<<SCAN_B, 256>>>();
    k_scan_final<<<SCAN_B, 256>>>();

    bool fork = g_aux.ok;
    if (fork) {
        cudaEventRecord(g_aux.evScan, 0);
        cudaStreamWaitEvent(g_aux.s2, g_aux.evScan, 0);
        // side stream: GEMM1 (needs dinv + W1f, not CSR)
        k_mgemm<0, false, 1, 1, false, false, 256, 256><<<dim3(2, GM), 256, 0, g_aux.s2>>>(x, nullptr, nullptr, nullptr);
        cudaEventRecord(g_aux.evJoin, g_aux.s2);
        // main stream: CSR fill (overlaps GEMM1)
        k_fill<<<EB, 256>>>(ei, E);
        cudaStreamWaitEvent(0, g_aux.evJoin, 0);
    } else {
        k_fill<<<EB, 256>>>(ei, E);
        k_mgemm<0, false, 1, 1, false, false, 256, 256><<<dim3(2, GM), 256>>>(x, nullptr, nullptr, nullptr);
    }

    // serial tail
    k_prop<256, true, 1, 1><<<(NN + 7) / 8, dim3(32, 8)>>>(b1);
    k_mgemm<2, true, 2, 2, false, false, 128, 256><<<dim3(1, GM), 256>>>(nullptr, nullptr, nullptr, nullptr);
    k_prop<128, false, 2, 2><<<(NN + 15) / 16, dim3(16, 16)>>>(b2);
    k_mgemm<4, true, 3, 0, true, true, 128, 128><<<dim3(2, GM), 256>>>(nullptr, bmu, blv, out);
}